// round 5
// baseline (speedup 1.0000x reference)
#include <cuda_runtime.h>
#include <math.h>

#define NB   32
#define NT   512
#define ND   1024
#define NCB  256
#define ROWS (NB*NT)     /* 16384 */
#define G3   (3*ND)      /* 3072  */

#define IDX_OFF  ((size_t)ROWS*ND)       /* 16777216 */
#define LOSS_OFF (IDX_OFF + (size_t)ROWS)/* 16793600 */

/* ------------ scratch (static device memory: allocation-free) ------------ */
__device__ float g_gi[(size_t)ROWS*G3];    /* 192 MB  gi_all (B,T,3d) */
__device__ float g_hs[(size_t)ROWS*ND];    /*  64 MB  context_hidden  */
__device__ float g_cproj[(size_t)ROWS*ND]; /*  64 MB  context_proj    */
__device__ float g_cn[NCB];                /* 0.5*||codebook_j||^2    */
__device__ float g_pos[NB];
__device__ float g_neg;
__device__ float g_sq;

/* ------------------------------- init ----------------------------------- */
__global__ void k_init(const float* __restrict__ cb) {
    int j = blockIdx.x;
    int tid = threadIdx.x;
    const float* row = cb + (size_t)j * ND;
    float s = 0.f;
    for (int v = tid; v < ND; v += 256) { float x = row[v]; s += x * x; }
    #pragma unroll
    for (int o = 16; o; o >>= 1) s += __shfl_down_sync(0xffffffffu, s, o);
    __shared__ float red[8];
    if ((tid & 31) == 0) red[tid >> 5] = s;
    __syncthreads();
    if (tid == 0) { float t = 0.f; for (int w = 0; w < 8; w++) t += red[w]; g_cn[j] = 0.5f * t; }
    if (j == 0) {
        if (tid < NB) g_pos[tid] = 0.f;
        if (tid == 32) g_neg = 0.f;
        if (tid == 33) g_sq = 0.f;
    }
}

/* ----------------------------- quantize ---------------------------------- */
/* Block: 32 rows vs all 256 codewords. Thread t owns codeword t, acc[32]. */
__global__ __launch_bounds__(256) void k_quant(const float* __restrict__ feat,
                                               const float* __restrict__ cb,
                                               float* __restrict__ outq,
                                               float* __restrict__ outidx) {
    __shared__ __align__(16) float cS[NCB * 36]; /* codebook tile; reused for scores */
    __shared__ __align__(16) float fS[32 * 32];
    __shared__ int   bestS[32];
    __shared__ float redS[8];
    int tid = threadIdx.x;
    int row0 = blockIdx.x * 32;

    float acc[32];
    #pragma unroll
    for (int m = 0; m < 32; m++) acc[m] = 0.f;

    for (int kb = 0; kb < ND; kb += 32) {
        { /* feature tile 32x32 */
            int fr = tid >> 3, fk = (tid & 7) * 4;
            *(float4*)&fS[fr * 32 + fk] =
                *(const float4*)&feat[(size_t)(row0 + fr) * ND + kb + fk];
        }
        #pragma unroll
        for (int v = 0; v < 8; v++) { /* codebook tile 256x32 */
            int li = tid + 256 * v;
            int cr = li >> 3, ck = (li & 7) * 4;
            *(float4*)&cS[cr * 36 + ck] =
                *(const float4*)&cb[(size_t)cr * ND + kb + ck];
        }
        __syncthreads();
        #pragma unroll
        for (int kk = 0; kk < 32; kk += 4) {
            float4 c4 = *(const float4*)&cS[tid * 36 + kk];
            #pragma unroll
            for (int m = 0; m < 32; m++) {
                float4 f4v = *(const float4*)&fS[m * 32 + kk];
                acc[m] += f4v.x * c4.x + f4v.y * c4.y + f4v.z * c4.z + f4v.w * c4.w;
            }
        }
        __syncthreads();
    }

    float half_cn = g_cn[tid];
    #pragma unroll
    for (int m = 0; m < 32; m++) cS[m * 256 + tid] = half_cn - acc[m];
    __syncthreads();

    int w = tid >> 5, lane = tid & 31;
    for (int mi = 0; mi < 4; mi++) {           /* warp w -> rows 4w..4w+3 */
        int m = w * 4 + mi;
        float bv = 3.0e38f; int bi = 0;
        #pragma unroll
        for (int j = 0; j < 8; j++) {
            int c = lane + 32 * j;
            float v = cS[m * 256 + c];
            if (v < bv) { bv = v; bi = c; }
        }
        #pragma unroll
        for (int o = 16; o; o >>= 1) {
            float v2 = __shfl_down_sync(0xffffffffu, bv, o);
            int   i2 = __shfl_down_sync(0xffffffffu, bi, o);
            if (v2 < bv || (v2 == bv && i2 < bi)) { bv = v2; bi = i2; }
        }
        if (lane == 0) bestS[m] = bi;
    }
    __syncthreads();

    if (tid < 32) outidx[row0 + tid] = (float)bestS[tid];

    float sq = 0.f;
    #pragma unroll 4
    for (int v = 0; v < 32; v++) {             /* gather + (f-q)^2 */
        int i4 = tid + 256 * v;
        int m = i4 >> 8;
        int kp = (i4 & 255) * 4;
        float4 q4 = *(const float4*)&cb[(size_t)bestS[m] * ND + kp];
        float4 f4v = *(const float4*)&feat[(size_t)(row0 + m) * ND + kp];
        *(float4*)&outq[(size_t)(row0 + m) * ND + kp] = q4;
        float dx = f4v.x - q4.x, dy = f4v.y - q4.y, dz = f4v.z - q4.z, dw = f4v.w - q4.w;
        sq += dx * dx + dy * dy + dz * dz + dw * dw;
    }
    #pragma unroll
    for (int o = 16; o; o >>= 1) sq += __shfl_down_sync(0xffffffffu, sq, o);
    if (lane == 0) redS[w] = sq;
    __syncthreads();
    if (tid == 0) { float t = 0.f; for (int i = 0; i < 8; i++) t += redS[i]; atomicAdd(&g_sq, t); }
}

/* ------------------------------ SGEMM ------------------------------------ */
/* C[M,N] = A[M,K] * Bm[N,K]^T + bias[N].  BM=128 BN=64 BK=16, 8x4/thread.  */
__global__ __launch_bounds__(256) void k_sgemm(const float* __restrict__ Aext, int a_sel,
                                               const float* __restrict__ Bm,
                                               const float* __restrict__ bias,
                                               int c_sel, int M, int N, int K) {
    const float* A = (a_sel == 0) ? Aext : g_hs;
    float* C = (c_sel == 0) ? g_gi : g_cproj;

    __shared__ __align__(16) float As[16 * 132];
    __shared__ __align__(16) float Bs[16 * 68];
    int tid = threadIdx.x;
    int tx = tid & 15, ty = tid >> 4;
    int nbase = blockIdx.x * 64, mbase = blockIdx.y * 128;

    float acc[8][4];
    #pragma unroll
    for (int i = 0; i < 8; i++)
        #pragma unroll
        for (int j = 0; j < 4; j++) acc[i][j] = 0.f;

    for (int kb = 0; kb < K; kb += 16) {
        #pragma unroll
        for (int v = 0; v < 2; v++) {
            int li = tid + 256 * v;
            int ar = li >> 2, ak = (li & 3) * 4;
            float4 a = *(const float4*)&A[(size_t)(mbase + ar) * K + kb + ak];
            As[(ak + 0) * 132 + ar] = a.x; As[(ak + 1) * 132 + ar] = a.y;
            As[(ak + 2) * 132 + ar] = a.z; As[(ak + 3) * 132 + ar] = a.w;
        }
        {
            int br = tid >> 2, bk = (tid & 3) * 4;
            float4 b = *(const float4*)&Bm[(size_t)(nbase + br) * K + kb + bk];
            Bs[(bk + 0) * 68 + br] = b.x; Bs[(bk + 1) * 68 + br] = b.y;
            Bs[(bk + 2) * 68 + br] = b.z; Bs[(bk + 3) * 68 + br] = b.w;
        }
        __syncthreads();
        #pragma unroll
        for (int kk = 0; kk < 16; kk++) {
            float4 a0 = *(const float4*)&As[kk * 132 + ty * 8];
            float4 a1 = *(const float4*)&As[kk * 132 + ty * 8 + 4];
            float4 b0 = *(const float4*)&Bs[kk * 68 + tx * 4];
            float av[8] = {a0.x, a0.y, a0.z, a0.w, a1.x, a1.y, a1.z, a1.w};
            float bv[4] = {b0.x, b0.y, b0.z, b0.w};
            #pragma unroll
            for (int i = 0; i < 8; i++)
                #pragma unroll
                for (int j = 0; j < 4; j++)
                    acc[i][j] += av[i] * bv[j];
        }
        __syncthreads();
    }
    float4 bb = *(const float4*)&bias[nbase + tx * 4];
    #pragma unroll
    for (int i = 0; i < 8; i++) {
        float4 o;
        o.x = acc[i][0] + bb.x; o.y = acc[i][1] + bb.y;
        o.z = acc[i][2] + bb.z; o.w = acc[i][3] + bb.w;
        *(float4*)&C[(size_t)(mbase + ty * 8 + i) * N + nbase + tx * 4] = o;
    }
}

/* ----------------------------- GRU step ----------------------------------- */
/* Block owns 8 hidden columns across all 3 gates (24 W_hh rows):
   gemm gh = h_{t-1} W_hh^T  for its tile, then fused gate update -> g_hs[t]. */
__global__ __launch_bounds__(256) void k_step(const float* __restrict__ Whh,
                                              const float* __restrict__ bhh, int t) {
    __shared__ __align__(16) float hS[32 * 132];
    __shared__ __align__(16) float wS[24 * 132];
    int tid = threadIdx.x;
    int r = tid & 31;     /* batch row  */
    int jj = tid >> 5;    /* 0..7 within j-tile */
    int jbase = blockIdx.x * 8;

    float a0 = 0.f, a1 = 0.f, a2 = 0.f;
    for (int kb = 0; kb < ND; kb += 128) {
        #pragma unroll
        for (int v = 0; v < 4; v++) {
            int li = tid + 256 * v;
            int hr = li >> 5, hk = (li & 31) * 4;
            float4 h4;
            if (t == 0) h4 = make_float4(0.f, 0.f, 0.f, 0.f);
            else h4 = *(const float4*)&g_hs[((size_t)hr * NT + (t - 1)) * ND + kb + hk];
            *(float4*)&hS[hr * 132 + hk] = h4;
        }
        #pragma unroll
        for (int v = 0; v < 3; v++) {
            int li = tid + 256 * v;
            int cr = li >> 5, ck = (li & 31) * 4;
            int wrow = (cr >> 3) * ND + jbase + (cr & 7);
            *(float4*)&wS[cr * 132 + ck] =
                *(const float4*)&Whh[(size_t)wrow * ND + kb + ck];
        }
        __syncthreads();
        #pragma unroll
        for (int kk = 0; kk < 128; kk += 4) {
            float4 h4 = *(const float4*)&hS[r * 132 + kk];
            float4 wr = *(const float4*)&wS[jj * 132 + kk];
            float4 wz = *(const float4*)&wS[(8 + jj) * 132 + kk];
            float4 wn = *(const float4*)&wS[(16 + jj) * 132 + kk];
            a0 += h4.x * wr.x + h4.y * wr.y + h4.z * wr.z + h4.w * wr.w;
            a1 += h4.x * wz.x + h4.y * wz.y + h4.z * wz.z + h4.w * wz.w;
            a2 += h4.x * wn.x + h4.y * wn.y + h4.z * wn.z + h4.w * wn.w;
        }
        __syncthreads();
    }
    int j = jbase + jj;
    int b = r;
    float ghr = a0 + bhh[j];
    float ghz = a1 + bhh[ND + j];
    float ghn = a2 + bhh[2 * ND + j];
    size_t gib = ((size_t)b * NT + t) * G3;
    float gir = g_gi[gib + j], giz = g_gi[gib + ND + j], gin = g_gi[gib + 2 * ND + j];
    float hp = (t == 0) ? 0.f : g_hs[((size_t)b * NT + (t - 1)) * ND + j];
    float rr = 1.0f / (1.0f + expf(-(gir + ghr)));
    float zz = 1.0f / (1.0f + expf(-(giz + ghz)));
    float nn = tanhf(gin + rr * ghn);
    g_hs[((size_t)b * NT + t) * ND + j] = (1.0f - zz) * nn + zz * hp;
}

/* ---------------------------- CP loss ------------------------------------- */
__global__ __launch_bounds__(256) void k_cp(const float* __restrict__ feat,
                                            const int* __restrict__ perm) {
    int l = blockIdx.x;
    int k = blockIdx.y + 1;
    if (l >= NT - k) return;
    __shared__ __align__(16) float hS[32 * 68];
    __shared__ __align__(16) float nS[32 * 68];
    __shared__ __align__(16) float pS[32 * 68];
    __shared__ int permS[32];
    __shared__ float redS[8];
    int tid = threadIdx.x;
    if (tid < 32) permS[tid] = perm[(k - 1) * NB + tid];
    __syncthreads();

    int b = tid & 31;
    int ng = tid >> 5;
    int n0 = ng * 4;
    float acc0 = 0.f, acc1 = 0.f, acc2 = 0.f, acc3 = 0.f, accP = 0.f;

    for (int kb = 0; kb < ND; kb += 64) {
        #pragma unroll
        for (int v = 0; v < 2; v++) {
            int li = tid + 256 * v;
            int row = li >> 4;
            int kk4 = (li & 15) * 4;
            *(float4*)&hS[row * 68 + kk4] =
                *(const float4*)&g_cproj[((size_t)row * NT + l) * ND + kb + kk4];
            *(float4*)&pS[row * 68 + kk4] =
                *(const float4*)&feat[((size_t)row * NT + l + k) * ND + kb + kk4];
            *(float4*)&nS[row * 68 + kk4] =
                *(const float4*)&feat[((size_t)permS[row] * NT + l) * ND + kb + kk4];
        }
        __syncthreads();
        #pragma unroll
        for (int kk = 0; kk < 64; kk += 4) {
            float4 h4 = *(const float4*)&hS[b * 68 + kk];
            float4 m0 = *(const float4*)&nS[(n0 + 0) * 68 + kk];
            float4 m1 = *(const float4*)&nS[(n0 + 1) * 68 + kk];
            float4 m2 = *(const float4*)&nS[(n0 + 2) * 68 + kk];
            float4 m3 = *(const float4*)&nS[(n0 + 3) * 68 + kk];
            acc0 += h4.x * m0.x + h4.y * m0.y + h4.z * m0.z + h4.w * m0.w;
            acc1 += h4.x * m1.x + h4.y * m1.y + h4.z * m1.z + h4.w * m1.w;
            acc2 += h4.x * m2.x + h4.y * m2.y + h4.z * m2.z + h4.w * m2.w;
            acc3 += h4.x * m3.x + h4.y * m3.y + h4.z * m3.z + h4.w * m3.w;
            if (ng == 0) {
                float4 p4 = *(const float4*)&pS[b * 68 + kk];
                accP += h4.x * p4.x + h4.y * p4.y + h4.z * p4.z + h4.w * p4.w;
            }
        }
        __syncthreads();
    }

    float nl = 0.f;
    nl += -logf(1.0f - 1.0f / (1.0f + expf(-acc0)) + 1e-8f);
    nl += -logf(1.0f - 1.0f / (1.0f + expf(-acc1)) + 1e-8f);
    nl += -logf(1.0f - 1.0f / (1.0f + expf(-acc2)) + 1e-8f);
    nl += -logf(1.0f - 1.0f / (1.0f + expf(-acc3)) + 1e-8f);
    int lane = tid & 31;
    #pragma unroll
    for (int o = 16; o; o >>= 1) nl += __shfl_down_sync(0xffffffffu, nl, o);
    if (lane == 0) redS[tid >> 5] = nl;
    __syncthreads();
    if (tid == 0) { float s = 0.f; for (int i = 0; i < 8; i++) s += redS[i]; atomicAdd(&g_neg, s); }
    if (ng == 0) {
        float pl = -logf(1.0f / (1.0f + expf(-accP)) + 1e-8f);
        atomicAdd(&g_pos[b], pl);
    }
}

/* ----------------------------- finalize ----------------------------------- */
__global__ void k_final(float* __restrict__ outLoss) {
    int b = threadIdx.x;
    if (b < NB) {
        float cp = (g_pos[b] + 0.25f * g_neg / 1024.0f) / 1527.0f;   /* K*(T-K)=3*509 */
        float vq = 1.25f * g_sq / 16777216.0f;                        /* B*T*d */
        outLoss[b] = cp + vq;
    }
}

/* ------------------------------ launch ------------------------------------ */
extern "C" void kernel_launch(void* const* d_in, const int* in_sizes, int n_in,
                              void* d_out, int out_size) {
    (void)in_sizes; (void)n_in; (void)out_size;
    const float* feat  = (const float*)d_in[0];
    const float* cb    = (const float*)d_in[1];
    const float* Wih   = (const float*)d_in[2];
    const float* Whh   = (const float*)d_in[3];
    const float* bih   = (const float*)d_in[4];
    const float* bhh   = (const float*)d_in[5];
    const float* Wproj = (const float*)d_in[6];
    const float* bproj = (const float*)d_in[7];
    const int*   perm  = (const int*)d_in[8];

    float* out     = (float*)d_out;
    float* outq    = out;                 /* quantized (B,T,d) */
    float* outidx  = out + IDX_OFF;       /* indices as float   */
    float* outloss = out + LOSS_OFF;      /* total_loss (B,)    */

    k_init<<<NCB, 256>>>(cb);
    k_quant<<<ROWS / 32, 256>>>(feat, cb, outq, outidx);
    /* gi_all = quantized @ W_ih^T + b_ih */
    k_sgemm<<<dim3(G3 / 64, ROWS / 128), 256>>>(outq, 0, Wih, bih, 0, ROWS, G3, ND);
    for (int t = 0; t < NT; t++)
        k_step<<<ND / 8, 256>>>(Whh, bhh, t);
    /* context_proj = hs @ W_proj^T + b_proj */
    k_sgemm<<<dim3(ND / 64, ROWS / 128), 256>>>(nullptr, 1, Wproj, bproj, 1, ROWS, ND, ND);
    k_cp<<<dim3(NT - 1, 3), 256>>>(feat, perm);
    k_final<<<1, 32>>>(outloss);
}

// round 6
// speedup vs baseline: 1.4425x; 1.4425x over previous
#include <cuda_runtime.h>
#include <math.h>

#define NB   32
#define NT   512
#define ND   1024
#define NCB  256
#define ROWS (NB*NT)     /* 16384 */
#define G3   (3*ND)      /* 3072  */
#define GRU_BLOCKS 128   /* 8 hidden columns per block */

#define IDX_OFF  ((size_t)ROWS*ND)       /* 16777216 */
#define LOSS_OFF (IDX_OFF + (size_t)ROWS)/* 16793600 */

/* ------------ scratch (static device memory: allocation-free) ------------ */
__device__ float g_hs[(size_t)ROWS*ND];    /*  64 MB  context_hidden  */
__device__ float g_cproj[(size_t)ROWS*ND]; /*  64 MB  context_proj    */
__device__ float g_gicb[(size_t)NCB*G3];   /*   3 MB  codebook@W_ih^T+b */
__device__ int   g_idx[ROWS];
__device__ float g_cn[NCB];                /* 0.5*||codebook_j||^2    */
__device__ float g_pos[NB];
__device__ float g_neg;
__device__ float g_sq;
__device__ int          g_bar_count;
__device__ volatile int g_bar_phase;

/* ------------------------------- init ----------------------------------- */
__global__ void k_init(const float* __restrict__ cb) {
    int j = blockIdx.x;
    int tid = threadIdx.x;
    const float* row = cb + (size_t)j * ND;
    float s = 0.f;
    for (int v = tid; v < ND; v += 256) { float x = row[v]; s += x * x; }
    #pragma unroll
    for (int o = 16; o; o >>= 1) s += __shfl_down_sync(0xffffffffu, s, o);
    __shared__ float red[8];
    if ((tid & 31) == 0) red[tid >> 5] = s;
    __syncthreads();
    if (tid == 0) { float t = 0.f; for (int w = 0; w < 8; w++) t += red[w]; g_cn[j] = 0.5f * t; }
    if (j == 0) {
        if (tid < NB) g_pos[tid] = 0.f;
        if (tid == 32) g_neg = 0.f;
        if (tid == 33) g_sq = 0.f;
        if (tid == 34) g_bar_count = 0;
        if (tid == 35) g_bar_phase = 0;
    }
}

/* ----------------------------- quantize ---------------------------------- */
__global__ __launch_bounds__(256) void k_quant(const float* __restrict__ feat,
                                               const float* __restrict__ cb,
                                               float* __restrict__ outq,
                                               float* __restrict__ outidx) {
    __shared__ __align__(16) float cS[NCB * 36]; /* codebook tile; reused for scores */
    __shared__ __align__(16) float fS[32 * 32];
    __shared__ int   bestS[32];
    __shared__ float redS[8];
    int tid = threadIdx.x;
    int row0 = blockIdx.x * 32;

    float acc[32];
    #pragma unroll
    for (int m = 0; m < 32; m++) acc[m] = 0.f;

    for (int kb = 0; kb < ND; kb += 32) {
        { /* feature tile 32x32 */
            int fr = tid >> 3, fk = (tid & 7) * 4;
            *(float4*)&fS[fr * 32 + fk] =
                *(const float4*)&feat[(size_t)(row0 + fr) * ND + kb + fk];
        }
        #pragma unroll
        for (int v = 0; v < 8; v++) { /* codebook tile 256x32 */
            int li = tid + 256 * v;
            int cr = li >> 3, ck = (li & 7) * 4;
            *(float4*)&cS[cr * 36 + ck] =
                *(const float4*)&cb[(size_t)cr * ND + kb + ck];
        }
        __syncthreads();
        #pragma unroll
        for (int kk = 0; kk < 32; kk += 4) {
            float4 c4 = *(const float4*)&cS[tid * 36 + kk];
            #pragma unroll
            for (int m = 0; m < 32; m++) {
                float4 f4v = *(const float4*)&fS[m * 32 + kk];
                acc[m] += f4v.x * c4.x + f4v.y * c4.y + f4v.z * c4.z + f4v.w * c4.w;
            }
        }
        __syncthreads();
    }

    float half_cn = g_cn[tid];
    #pragma unroll
    for (int m = 0; m < 32; m++) cS[m * 256 + tid] = half_cn - acc[m];
    __syncthreads();

    int w = tid >> 5, lane = tid & 31;
    for (int mi = 0; mi < 4; mi++) {
        int m = w * 4 + mi;
        float bv = 3.0e38f; int bi = 0;
        #pragma unroll
        for (int j = 0; j < 8; j++) {
            int c = lane + 32 * j;
            float v = cS[m * 256 + c];
            if (v < bv) { bv = v; bi = c; }
        }
        #pragma unroll
        for (int o = 16; o; o >>= 1) {
            float v2 = __shfl_down_sync(0xffffffffu, bv, o);
            int   i2 = __shfl_down_sync(0xffffffffu, bi, o);
            if (v2 < bv || (v2 == bv && i2 < bi)) { bv = v2; bi = i2; }
        }
        if (lane == 0) bestS[m] = bi;
    }
    __syncthreads();

    if (tid < 32) {
        outidx[row0 + tid] = (float)bestS[tid];
        g_idx[row0 + tid] = bestS[tid];
    }

    float sq = 0.f;
    #pragma unroll 4
    for (int v = 0; v < 32; v++) {
        int i4 = tid + 256 * v;
        int m = i4 >> 8;
        int kp = (i4 & 255) * 4;
        float4 q4 = *(const float4*)&cb[(size_t)bestS[m] * ND + kp];
        float4 f4v = *(const float4*)&feat[(size_t)(row0 + m) * ND + kp];
        *(float4*)&outq[(size_t)(row0 + m) * ND + kp] = q4;
        float dx = f4v.x - q4.x, dy = f4v.y - q4.y, dz = f4v.z - q4.z, dw = f4v.w - q4.w;
        sq += dx * dx + dy * dy + dz * dz + dw * dw;
    }
    #pragma unroll
    for (int o = 16; o; o >>= 1) sq += __shfl_down_sync(0xffffffffu, sq, o);
    if (lane == 0) redS[w] = sq;
    __syncthreads();
    if (tid == 0) { float t = 0.f; for (int i = 0; i < 8; i++) t += redS[i]; atomicAdd(&g_sq, t); }
}

/* ------------------------------ SGEMM ------------------------------------ */
/* C[M,N] = A[M,K] * Bm[N,K]^T + bias[N].  BM=128 BN=64 BK=16, 8x4/thread.  */
__global__ __launch_bounds__(256) void k_sgemm(const float* __restrict__ Aext, int a_sel,
                                               const float* __restrict__ Bm,
                                               const float* __restrict__ bias,
                                               int c_sel, int M, int N, int K) {
    const float* A = (a_sel == 0) ? Aext : g_hs;
    float* C = (c_sel == 0) ? g_gicb : g_cproj;

    __shared__ __align__(16) float As[16 * 132];
    __shared__ __align__(16) float Bs[16 * 68];
    int tid = threadIdx.x;
    int tx = tid & 15, ty = tid >> 4;
    int nbase = blockIdx.x * 64, mbase = blockIdx.y * 128;

    float acc[8][4];
    #pragma unroll
    for (int i = 0; i < 8; i++)
        #pragma unroll
        for (int j = 0; j < 4; j++) acc[i][j] = 0.f;

    for (int kb = 0; kb < K; kb += 16) {
        #pragma unroll
        for (int v = 0; v < 2; v++) {
            int li = tid + 256 * v;
            int ar = li >> 2, ak = (li & 3) * 4;
            float4 a = *(const float4*)&A[(size_t)(mbase + ar) * K + kb + ak];
            As[(ak + 0) * 132 + ar] = a.x; As[(ak + 1) * 132 + ar] = a.y;
            As[(ak + 2) * 132 + ar] = a.z; As[(ak + 3) * 132 + ar] = a.w;
        }
        {
            int br = tid >> 2, bk = (tid & 3) * 4;
            float4 b = *(const float4*)&Bm[(size_t)(nbase + br) * K + kb + bk];
            Bs[(bk + 0) * 68 + br] = b.x; Bs[(bk + 1) * 68 + br] = b.y;
            Bs[(bk + 2) * 68 + br] = b.z; Bs[(bk + 3) * 68 + br] = b.w;
        }
        __syncthreads();
        #pragma unroll
        for (int kk = 0; kk < 16; kk++) {
            float4 a0 = *(const float4*)&As[kk * 132 + ty * 8];
            float4 a1 = *(const float4*)&As[kk * 132 + ty * 8 + 4];
            float4 b0 = *(const float4*)&Bs[kk * 68 + tx * 4];
            float av[8] = {a0.x, a0.y, a0.z, a0.w, a1.x, a1.y, a1.z, a1.w};
            float bv[4] = {b0.x, b0.y, b0.z, b0.w};
            #pragma unroll
            for (int i = 0; i < 8; i++)
                #pragma unroll
                for (int j = 0; j < 4; j++)
                    acc[i][j] += av[i] * bv[j];
        }
        __syncthreads();
    }
    float4 bb = *(const float4*)&bias[nbase + tx * 4];
    #pragma unroll
    for (int i = 0; i < 8; i++) {
        float4 o;
        o.x = acc[i][0] + bb.x; o.y = acc[i][1] + bb.y;
        o.z = acc[i][2] + bb.z; o.w = acc[i][3] + bb.w;
        *(float4*)&C[(size_t)(mbase + ty * 8 + i) * N + nbase + tx * 4] = o;
    }
}

/* ------------------------- persistent GRU --------------------------------- */
/* 128 blocks x 256 threads, 1 block/SM. Block owns 8 hidden columns (24 W
   rows), W resident in smem for all 512 steps. Thread = (r=lane batch row,
   jgroup of 2 cols x 3 gates, khalf) -> 6 accumulators; k-split reduced via
   smem. Steps separated by a software grid barrier. */
#define GRU_SMEM_FLOATS (24*1024 + 2*32*132)
#define GRU_SMEM_BYTES  (GRU_SMEM_FLOATS*4)

__global__ __launch_bounds__(256, 1) void k_gru(const float* __restrict__ Whh,
                                                const float* __restrict__ bhh) {
    extern __shared__ float sm[];
    float* wS = sm;                    /* 24 x 1024 */
    float* hA = sm + 24 * 1024;       /* 32 x 132  */
    float* hB = hA + 32 * 132;

    const int tid  = threadIdx.x;
    const int lane = tid & 31;          /* batch row r */
    const int w    = tid >> 5;
    const int jg   = w & 3;             /* column pair 0..3 */
    const int kh   = w >> 2;            /* k half 0/1 */
    const int jbase = blockIdx.x * 8;

    /* ---- stage W_hh tile (once) ---- */
    #pragma unroll
    for (int v = 0; v < 24; v++) {
        int li = tid + 256 * v;
        int wr = li >> 8;               /* 0..23 = gate*8 + jj */
        int wk = (li & 255) * 4;
        int g = wr >> 3, jj = wr & 7;
        *(float4*)&wS[wr * 1024 + wk] =
            *(const float4*)&Whh[((size_t)(g * ND + jbase + jj)) * ND + wk];
    }

    /* per-thread W row pointers (2 cols x 3 gates) */
    const float* wp0 = wS + (2 * jg    ) * 1024;
    const float* wp1 = wS + (2 * jg + 1) * 1024;
    const float* wp2 = wS + (8 + 2 * jg    ) * 1024;
    const float* wp3 = wS + (8 + 2 * jg + 1) * 1024;
    const float* wp4 = wS + (16 + 2 * jg    ) * 1024;
    const float* wp5 = wS + (16 + 2 * jg + 1) * 1024;

    /* bias preload (used by khalf==0 epilogue threads) */
    const int j0 = jbase + 2 * jg, j1 = j0 + 1;
    const float bR0 = bhh[j0],          bR1 = bhh[j1];
    const float bZ0 = bhh[ND + j0],     bZ1 = bhh[ND + j1];
    const float bN0 = bhh[2 * ND + j0], bN1 = bhh[2 * ND + j1];

    /* constant staging offsets: v-th vector is row (w+8v), cols lane*4.. */
    size_t groff[4]; int soff[4];
    #pragma unroll
    for (int v = 0; v < 4; v++) {
        int hr = w + 8 * v;
        groff[v] = (size_t)hr * NT * ND + lane * 4;
        soff[v]  = hr * 132 + lane * 4;
    }

    __syncthreads();

    for (int t = 0; t < NT; t++) {
        float a0 = 0.f, a1 = 0.f, a2 = 0.f, a3 = 0.f, a4 = 0.f, a5 = 0.f;

        if (t > 0) {
            const size_t tb = (size_t)(t - 1) * ND;
            float4 pre[4];
            #pragma unroll
            for (int v = 0; v < 4; v++)
                pre[v] = __ldcg((const float4*)(g_hs + groff[v] + tb));

            #pragma unroll 1
            for (int c = 0; c < 8; c++) {
                float* buf = (c & 1) ? hB : hA;
                #pragma unroll
                for (int v = 0; v < 4; v++)
                    *(float4*)&buf[soff[v]] = pre[v];
                __syncthreads();

                if (c < 7) {
                    size_t off = tb + (c + 1) * 128;
                    #pragma unroll
                    for (int v = 0; v < 4; v++)
                        pre[v] = __ldcg((const float4*)(g_hs + groff[v] + off));
                }

                const int kb = c * 128 + kh * 64;
                const float* hp = buf + lane * 132 + kh * 64;
                #pragma unroll
                for (int kk = 0; kk < 64; kk += 4) {
                    float4 h4 = *(const float4*)(hp + kk);
                    float4 u0 = *(const float4*)(wp0 + kb + kk);
                    float4 u1 = *(const float4*)(wp1 + kb + kk);
                    float4 u2 = *(const float4*)(wp2 + kb + kk);
                    float4 u3 = *(const float4*)(wp3 + kb + kk);
                    float4 u4 = *(const float4*)(wp4 + kb + kk);
                    float4 u5 = *(const float4*)(wp5 + kb + kk);
                    a0 += h4.x * u0.x + h4.y * u0.y + h4.z * u0.z + h4.w * u0.w;
                    a1 += h4.x * u1.x + h4.y * u1.y + h4.z * u1.z + h4.w * u1.w;
                    a2 += h4.x * u2.x + h4.y * u2.y + h4.z * u2.z + h4.w * u2.w;
                    a3 += h4.x * u3.x + h4.y * u3.y + h4.z * u3.z + h4.w * u3.w;
                    a4 += h4.x * u4.x + h4.y * u4.y + h4.z * u4.z + h4.w * u4.w;
                    a5 += h4.x * u5.x + h4.y * u5.y + h4.z * u5.z + h4.w * u5.w;
                }
                __syncthreads();   /* before buffer reuse / reduction */
            }
        }

        /* k-split reduction: khalf1 -> smem, khalf0 adds */
        if (kh == 1) {
            float* rb = hA + (tid - 128) * 6;
            rb[0] = a0; rb[1] = a1; rb[2] = a2; rb[3] = a3; rb[4] = a4; rb[5] = a5;
        }
        __syncthreads();
        if (kh == 0) {
            const float* rb = hA + tid * 6;
            a0 += rb[0]; a1 += rb[1]; a2 += rb[2]; a3 += rb[3]; a4 += rb[4]; a5 += rb[5];

            int idxv = g_idx[lane * NT + t];
            const float* gic = g_gicb + (size_t)idxv * G3;
            size_t hrow = ((size_t)lane * NT + t) * ND;
            size_t prow = hrow - ND;

            /* col 0 */
            {
                float ghr = a0 + bR0, ghz = a2 + bZ0, ghn = a4 + bN0;
                float gir = gic[j0], giz = gic[ND + j0], gin = gic[2 * ND + j0];
                float hpv = (t == 0) ? 0.f : __ldcg(&g_hs[prow + j0]);
                float rr = 1.0f / (1.0f + expf(-(gir + ghr)));
                float zz = 1.0f / (1.0f + expf(-(giz + ghz)));
                float nn = tanhf(gin + rr * ghn);
                g_hs[hrow + j0] = (1.0f - zz) * nn + zz * hpv;
            }
            /* col 1 */
            {
                float ghr = a1 + bR1, ghz = a3 + bZ1, ghn = a5 + bN1;
                float gir = gic[j1], giz = gic[ND + j1], gin = gic[2 * ND + j1];
                float hpv = (t == 0) ? 0.f : __ldcg(&g_hs[prow + j1]);
                float rr = 1.0f / (1.0f + expf(-(gir + ghr)));
                float zz = 1.0f / (1.0f + expf(-(giz + ghz)));
                float nn = tanhf(gin + rr * ghn);
                g_hs[hrow + j1] = (1.0f - zz) * nn + zz * hpv;
            }
        }

        /* grid barrier */
        __threadfence();
        __syncthreads();
        if (tid == 0) {
            if (atomicAdd(&g_bar_count, 1) == GRU_BLOCKS - 1) {
                g_bar_count = 0;
                __threadfence();
                g_bar_phase = t + 1;
            } else {
                while (g_bar_phase <= t) { }
                __threadfence();
            }
        }
        __syncthreads();
    }
}

/* ---------------------------- CP loss ------------------------------------- */
__global__ __launch_bounds__(256) void k_cp(const float* __restrict__ feat,
                                            const int* __restrict__ perm) {
    int l = blockIdx.x;
    int k = blockIdx.y + 1;
    if (l >= NT - k) return;
    __shared__ __align__(16) float hS[32 * 68];
    __shared__ __align__(16) float nS[32 * 68];
    __shared__ __align__(16) float pS[32 * 68];
    __shared__ int permS[32];
    __shared__ float redS[8];
    int tid = threadIdx.x;
    if (tid < 32) permS[tid] = perm[(k - 1) * NB + tid];
    __syncthreads();

    int b = tid & 31;
    int ng = tid >> 5;
    int n0 = ng * 4;
    float acc0 = 0.f, acc1 = 0.f, acc2 = 0.f, acc3 = 0.f, accP = 0.f;

    for (int kb = 0; kb < ND; kb += 64) {
        #pragma unroll
        for (int v = 0; v < 2; v++) {
            int li = tid + 256 * v;
            int row = li >> 4;
            int kk4 = (li & 15) * 4;
            *(float4*)&hS[row * 68 + kk4] =
                *(const float4*)&g_cproj[((size_t)row * NT + l) * ND + kb + kk4];
            *(float4*)&pS[row * 68 + kk4] =
                *(const float4*)&feat[((size_t)row * NT + l + k) * ND + kb + kk4];
            *(float4*)&nS[row * 68 + kk4] =
                *(const float4*)&feat[((size_t)permS[row] * NT + l) * ND + kb + kk4];
        }
        __syncthreads();
        #pragma unroll
        for (int kk = 0; kk < 64; kk += 4) {
            float4 h4 = *(const float4*)&hS[b * 68 + kk];
            float4 m0 = *(const float4*)&nS[(n0 + 0) * 68 + kk];
            float4 m1 = *(const float4*)&nS[(n0 + 1) * 68 + kk];
            float4 m2 = *(const float4*)&nS[(n0 + 2) * 68 + kk];
            float4 m3 = *(const float4*)&nS[(n0 + 3) * 68 + kk];
            acc0 += h4.x * m0.x + h4.y * m0.y + h4.z * m0.z + h4.w * m0.w;
            acc1 += h4.x * m1.x + h4.y * m1.y + h4.z * m1.z + h4.w * m1.w;
            acc2 += h4.x * m2.x + h4.y * m2.y + h4.z * m2.z + h4.w * m2.w;
            acc3 += h4.x * m3.x + h4.y * m3.y + h4.z * m3.z + h4.w * m3.w;
            if (ng == 0) {
                float4 p4 = *(const float4*)&pS[b * 68 + kk];
                accP += h4.x * p4.x + h4.y * p4.y + h4.z * p4.z + h4.w * p4.w;
            }
        }
        __syncthreads();
    }

    float nl = 0.f;
    nl += -logf(1.0f - 1.0f / (1.0f + expf(-acc0)) + 1e-8f);
    nl += -logf(1.0f - 1.0f / (1.0f + expf(-acc1)) + 1e-8f);
    nl += -logf(1.0f - 1.0f / (1.0f + expf(-acc2)) + 1e-8f);
    nl += -logf(1.0f - 1.0f / (1.0f + expf(-acc3)) + 1e-8f);
    int lane = tid & 31;
    #pragma unroll
    for (int o = 16; o; o >>= 1) nl += __shfl_down_sync(0xffffffffu, nl, o);
    if (lane == 0) redS[tid >> 5] = nl;
    __syncthreads();
    if (tid == 0) { float s = 0.f; for (int i = 0; i < 8; i++) s += redS[i]; atomicAdd(&g_neg, s); }
    if (ng == 0) {
        float pl = -logf(1.0f / (1.0f + expf(-accP)) + 1e-8f);
        atomicAdd(&g_pos[b], pl);
    }
}

/* ----------------------------- finalize ----------------------------------- */
__global__ void k_final(float* __restrict__ outLoss) {
    int b = threadIdx.x;
    if (b < NB) {
        float cp = (g_pos[b] + 0.25f * g_neg / 1024.0f) / 1527.0f;   /* K*(T-K)=3*509 */
        float vq = 1.25f * g_sq / 16777216.0f;                        /* B*T*d */
        outLoss[b] = cp + vq;
    }
}

/* ------------------------------ launch ------------------------------------ */
extern "C" void kernel_launch(void* const* d_in, const int* in_sizes, int n_in,
                              void* d_out, int out_size) {
    (void)in_sizes; (void)n_in; (void)out_size;
    const float* feat  = (const float*)d_in[0];
    const float* cb    = (const float*)d_in[1];
    const float* Wih   = (const float*)d_in[2];
    const float* Whh   = (const float*)d_in[3];
    const float* bih   = (const float*)d_in[4];
    const float* bhh   = (const float*)d_in[5];
    const float* Wproj = (const float*)d_in[6];
    const float* bproj = (const float*)d_in[7];
    const int*   perm  = (const int*)d_in[8];

    float* out     = (float*)d_out;
    float* outq    = out;                 /* quantized (B,T,d) */
    float* outidx  = out + IDX_OFF;       /* indices as float   */
    float* outloss = out + LOSS_OFF;      /* total_loss (B,)    */

    cudaFuncSetAttribute(k_gru, cudaFuncAttributeMaxDynamicSharedMemorySize,
                         GRU_SMEM_BYTES);

    k_init<<<NCB, 256>>>(cb);
    k_quant<<<ROWS / 32, 256>>>(feat, cb, outq, outidx);
    /* gi table: (codebook @ W_ih^T + b_ih), 256 x 3072 */
    k_sgemm<<<dim3(G3 / 64, NCB / 128), 256>>>(cb, 0, Wih, bih, 0, NCB, G3, ND);
    /* persistent GRU over all 512 steps */
    k_gru<<<GRU_BLOCKS, 256, GRU_SMEM_BYTES>>>(Whh, bhh);
    /* context_proj = hs @ W_proj^T + b_proj */
    k_sgemm<<<dim3(ND / 64, ROWS / 128), 256>>>(nullptr, 1, Wproj, bproj, 1, ROWS, ND, ND);
    k_cp<<<dim3(NT - 1, 3), 256>>>(feat, perm);
    k_final<<<1, 32>>>(outloss);
}

// round 7
// speedup vs baseline: 1.6877x; 1.1700x over previous
#include <cuda_runtime.h>
#include <math.h>

#define NB   32
#define NT   512
#define ND   1024
#define NCB  256
#define ROWS (NB*NT)     /* 16384 */
#define G3   (3*ND)      /* 3072  */
#define GRU_BLOCKS 128   /* 8 hidden columns per block */

#define IDX_OFF  ((size_t)ROWS*ND)       /* 16777216 */
#define LOSS_OFF (IDX_OFF + (size_t)ROWS)/* 16793600 */

/* ------------ scratch (static device memory: allocation-free) ------------ */
__device__ float g_hs[(size_t)ROWS*ND];    /*  64 MB  context_hidden  */
__device__ float g_cproj[(size_t)ROWS*ND]; /*  64 MB  context_proj    */
__device__ float g_gicb[(size_t)NCB*G3];   /*   3 MB  codebook@W_ih^T+b */
__device__ int   g_idx[ROWS];
__device__ float g_cn[NCB];                /* 0.5*||codebook_j||^2    */
__device__ float g_pos[NB];
__device__ float g_neg;
__device__ float g_sq;
__device__ int          g_bar_count;
__device__ volatile int g_bar_phase;

/* --------------------------- f32x2 helpers -------------------------------- */
typedef unsigned long long ull;
__device__ __forceinline__ ull ffma2(ull a, ull b, ull c) {
    ull d;
    asm("fma.rn.f32x2 %0, %1, %2, %3;" : "=l"(d) : "l"(a), "l"(b), "l"(c));
    return d;
}
__device__ __forceinline__ ull dup2(float x) {
    ull d; asm("mov.b64 %0, {%1, %1};" : "=l"(d) : "f"(x)); return d;
}
__device__ __forceinline__ float2 unpk(ull v) {
    float2 r; asm("mov.b64 {%0, %1}, %2;" : "=f"(r.x), "=f"(r.y) : "l"(v)); return r;
}

/* ------------------------------- init ----------------------------------- */
__global__ void k_init(const float* __restrict__ cb) {
    int j = blockIdx.x;
    int tid = threadIdx.x;
    const float* row = cb + (size_t)j * ND;
    float s = 0.f;
    for (int v = tid; v < ND; v += 256) { float x = row[v]; s += x * x; }
    #pragma unroll
    for (int o = 16; o; o >>= 1) s += __shfl_down_sync(0xffffffffu, s, o);
    __shared__ float red[8];
    if ((tid & 31) == 0) red[tid >> 5] = s;
    __syncthreads();
    if (tid == 0) { float t = 0.f; for (int w = 0; w < 8; w++) t += red[w]; g_cn[j] = 0.5f * t; }
    if (j == 0) {
        if (tid < NB) g_pos[tid] = 0.f;
        if (tid == 32) g_neg = 0.f;
        if (tid == 33) g_sq = 0.f;
        if (tid == 34) g_bar_count = 0;
        if (tid == 35) g_bar_phase = 0;
    }
}

/* ----------------------------- quantize ---------------------------------- */
__global__ __launch_bounds__(256) void k_quant(const float* __restrict__ feat,
                                               const float* __restrict__ cb,
                                               float* __restrict__ outq,
                                               float* __restrict__ outidx) {
    __shared__ __align__(16) float cS[NCB * 36]; /* codebook tile; reused for scores */
    __shared__ __align__(16) float fS[32 * 32];
    __shared__ int   bestS[32];
    __shared__ float redS[8];
    int tid = threadIdx.x;
    int row0 = blockIdx.x * 32;

    ull acc2[32];
    #pragma unroll
    for (int m = 0; m < 32; m++) acc2[m] = 0ull;

    for (int kb = 0; kb < ND; kb += 32) {
        { /* feature tile 32x32 */
            int fr = tid >> 3, fk = (tid & 7) * 4;
            *(float4*)&fS[fr * 32 + fk] =
                *(const float4*)&feat[(size_t)(row0 + fr) * ND + kb + fk];
        }
        #pragma unroll
        for (int v = 0; v < 8; v++) { /* codebook tile 256x32 */
            int li = tid + 256 * v;
            int cr = li >> 3, ck = (li & 7) * 4;
            *(float4*)&cS[cr * 36 + ck] =
                *(const float4*)&cb[(size_t)cr * ND + kb + ck];
        }
        __syncthreads();
        #pragma unroll
        for (int kk = 0; kk < 32; kk += 4) {
            ulonglong2 c2 = *(const ulonglong2*)&cS[tid * 36 + kk];
            #pragma unroll
            for (int m = 0; m < 32; m++) {
                ulonglong2 f2 = *(const ulonglong2*)&fS[m * 32 + kk];
                acc2[m] = ffma2(f2.x, c2.x, acc2[m]);
                acc2[m] = ffma2(f2.y, c2.y, acc2[m]);
            }
        }
        __syncthreads();
    }

    float half_cn = g_cn[tid];
    #pragma unroll
    for (int m = 0; m < 32; m++) {
        float2 p = unpk(acc2[m]);
        cS[m * 256 + tid] = half_cn - (p.x + p.y);
    }
    __syncthreads();

    int w = tid >> 5, lane = tid & 31;
    for (int mi = 0; mi < 4; mi++) {
        int m = w * 4 + mi;
        float bv = 3.0e38f; int bi = 0;
        #pragma unroll
        for (int j = 0; j < 8; j++) {
            int c = lane + 32 * j;
            float v = cS[m * 256 + c];
            if (v < bv) { bv = v; bi = c; }
        }
        #pragma unroll
        for (int o = 16; o; o >>= 1) {
            float v2 = __shfl_down_sync(0xffffffffu, bv, o);
            int   i2 = __shfl_down_sync(0xffffffffu, bi, o);
            if (v2 < bv || (v2 == bv && i2 < bi)) { bv = v2; bi = i2; }
        }
        if (lane == 0) bestS[m] = bi;
    }
    __syncthreads();

    if (tid < 32) {
        outidx[row0 + tid] = (float)bestS[tid];
        g_idx[row0 + tid] = bestS[tid];
    }

    float sq = 0.f;
    #pragma unroll 4
    for (int v = 0; v < 32; v++) {
        int i4 = tid + 256 * v;
        int m = i4 >> 8;
        int kp = (i4 & 255) * 4;
        float4 q4 = *(const float4*)&cb[(size_t)bestS[m] * ND + kp];
        float4 f4v = *(const float4*)&feat[(size_t)(row0 + m) * ND + kp];
        *(float4*)&outq[(size_t)(row0 + m) * ND + kp] = q4;
        float dx = f4v.x - q4.x, dy = f4v.y - q4.y, dz = f4v.z - q4.z, dw = f4v.w - q4.w;
        sq += dx * dx + dy * dy + dz * dz + dw * dw;
    }
    #pragma unroll
    for (int o = 16; o; o >>= 1) sq += __shfl_down_sync(0xffffffffu, sq, o);
    if (lane == 0) redS[w] = sq;
    __syncthreads();
    if (tid == 0) { float t = 0.f; for (int i = 0; i < 8; i++) t += redS[i]; atomicAdd(&g_sq, t); }
}

/* ------------------------------ SGEMM (f32x2) ----------------------------- */
/* C[M,N] = A[M,K] * Bm[N,K]^T + bias[N].  BM=128 BN=64 BK=16, 8x4/thread.  */
__global__ __launch_bounds__(256) void k_sgemm(const float* __restrict__ Aext, int a_sel,
                                               const float* __restrict__ Bm,
                                               const float* __restrict__ bias,
                                               int c_sel, int M, int N, int K) {
    const float* A = (a_sel == 0) ? Aext : g_hs;
    float* C = (c_sel == 0) ? g_gicb : g_cproj;

    __shared__ __align__(16) float As[16 * 132];
    __shared__ __align__(16) float Bs[16 * 68];
    int tid = threadIdx.x;
    int tx = tid & 15, ty = tid >> 4;
    int nbase = blockIdx.x * 64, mbase = blockIdx.y * 128;

    ull acc2[4][4];  /* row-pairs x 4 cols */
    #pragma unroll
    for (int i = 0; i < 4; i++)
        #pragma unroll
        for (int j = 0; j < 4; j++) acc2[i][j] = 0ull;

    for (int kb = 0; kb < K; kb += 16) {
        #pragma unroll
        for (int v = 0; v < 2; v++) {
            int li = tid + 256 * v;
            int ar = li >> 2, ak = (li & 3) * 4;
            float4 a = *(const float4*)&A[(size_t)(mbase + ar) * K + kb + ak];
            As[(ak + 0) * 132 + ar] = a.x; As[(ak + 1) * 132 + ar] = a.y;
            As[(ak + 2) * 132 + ar] = a.z; As[(ak + 3) * 132 + ar] = a.w;
        }
        {
            int br = tid >> 2, bk = (tid & 3) * 4;
            float4 b = *(const float4*)&Bm[(size_t)(nbase + br) * K + kb + bk];
            Bs[(bk + 0) * 68 + br] = b.x; Bs[(bk + 1) * 68 + br] = b.y;
            Bs[(bk + 2) * 68 + br] = b.z; Bs[(bk + 3) * 68 + br] = b.w;
        }
        __syncthreads();
        #pragma unroll
        for (int kk = 0; kk < 16; kk++) {
            ulonglong2 aL = *(const ulonglong2*)&As[kk * 132 + ty * 8];
            ulonglong2 aH = *(const ulonglong2*)&As[kk * 132 + ty * 8 + 4];
            float4 b0 = *(const float4*)&Bs[kk * 68 + tx * 4];
            ull bd0 = dup2(b0.x), bd1 = dup2(b0.y), bd2 = dup2(b0.z), bd3 = dup2(b0.w);
            acc2[0][0] = ffma2(aL.x, bd0, acc2[0][0]);
            acc2[0][1] = ffma2(aL.x, bd1, acc2[0][1]);
            acc2[0][2] = ffma2(aL.x, bd2, acc2[0][2]);
            acc2[0][3] = ffma2(aL.x, bd3, acc2[0][3]);
            acc2[1][0] = ffma2(aL.y, bd0, acc2[1][0]);
            acc2[1][1] = ffma2(aL.y, bd1, acc2[1][1]);
            acc2[1][2] = ffma2(aL.y, bd2, acc2[1][2]);
            acc2[1][3] = ffma2(aL.y, bd3, acc2[1][3]);
            acc2[2][0] = ffma2(aH.x, bd0, acc2[2][0]);
            acc2[2][1] = ffma2(aH.x, bd1, acc2[2][1]);
            acc2[2][2] = ffma2(aH.x, bd2, acc2[2][2]);
            acc2[2][3] = ffma2(aH.x, bd3, acc2[2][3]);
            acc2[3][0] = ffma2(aH.y, bd0, acc2[3][0]);
            acc2[3][1] = ffma2(aH.y, bd1, acc2[3][1]);
            acc2[3][2] = ffma2(aH.y, bd2, acc2[3][2]);
            acc2[3][3] = ffma2(aH.y, bd3, acc2[3][3]);
        }
        __syncthreads();
    }
    float4 bb = *(const float4*)&bias[nbase + tx * 4];
    #pragma unroll
    for (int i2 = 0; i2 < 4; i2++) {
        float2 p0 = unpk(acc2[i2][0]);
        float2 p1 = unpk(acc2[i2][1]);
        float2 p2 = unpk(acc2[i2][2]);
        float2 p3 = unpk(acc2[i2][3]);
        float4 o0, o1;
        o0.x = p0.x + bb.x; o0.y = p1.x + bb.y; o0.z = p2.x + bb.z; o0.w = p3.x + bb.w;
        o1.x = p0.y + bb.x; o1.y = p1.y + bb.y; o1.z = p2.y + bb.z; o1.w = p3.y + bb.w;
        *(float4*)&C[(size_t)(mbase + ty * 8 + 2 * i2    ) * N + nbase + tx * 4] = o0;
        *(float4*)&C[(size_t)(mbase + ty * 8 + 2 * i2 + 1) * N + nbase + tx * 4] = o1;
    }
}

/* ------------------------- persistent GRU --------------------------------- */
/* 128 blocks x 256 threads, 1/SM. Block owns 8 hidden cols (24 W rows) with
   W resident in smem. lane = batch, warp = 128-wide k-chunk, warp covers all
   24 rows: one broadcast W float4 feeds 32 batches at once. h_prev staged to
   smem XOR-swizzled; h[b][own column] carried in a register across steps.
   f32x2 FMA, k-split reduction via smem, software grid barrier per step. */
#define GRU_SMEM_FLOATS (24*1024 + 32*1024)
#define GRU_SMEM_BYTES  (GRU_SMEM_FLOATS*4)      /* 229376 <= 232448 */

__global__ __launch_bounds__(256, 1) void k_gru(const float* __restrict__ Whh,
                                                const float* __restrict__ bhh) {
    extern __shared__ float sm[];
    float* wS = sm;               /* 24 x 1024 */
    float* hS = sm + 24 * 1024;   /* 32 x 1024, chunk-XOR swizzled */
    float* red = hS;              /* 24 x 8 x 32 floats, overlays hS */

    const int tid = threadIdx.x;
    const int w   = tid >> 5;     /* warp = k-chunk id (0..7) */
    const int b   = tid & 31;     /* lane = batch row        */
    const int jbase = blockIdx.x * 8;

    /* ---- stage W_hh tile once ---- */
    #pragma unroll
    for (int v = 0; v < 24; v++) {
        int li = tid + 256 * v;          /* float4 index 0..6143 */
        int r = li >> 8;                 /* 0..23 */
        int k4 = (li & 255) * 4;
        int g = r >> 3, jj = r & 7;
        *(float4*)&wS[r * 1024 + k4] =
            *(const float4*)&Whh[((size_t)(g * ND + jbase + jj)) * ND + k4];
    }

    /* epilogue identity: thread owns (batch eb, column ej) */
    const int eb = b, ejj = w;
    const int ej = jbase + ejj;
    const float bR = bhh[ej], bZ = bhh[ND + ej], bN = bhh[2 * ND + ej];

    /* staging identity */
    const int sb = tid >> 3, skq = tid & 7;
    const int sswz = sb & 7;
    const int bsw = b & 7;

    __syncthreads();

    float hp = 0.f;   /* h_{t-1}[eb][ej], register-carried */

    for (int t = 0; t < NT; t++) {
        /* prefetch gi (independent of h) */
        int idxv = g_idx[eb * NT + t];
        const float* gic = g_gicb + (size_t)idxv * G3;
        float gir = gic[ej], giz = gic[ND + ej], gin = gic[2 * ND + ej];

        float ghr = 0.f, ghz = 0.f, ghn = 0.f;

        if (t > 0) {
            /* ---- stage h_{t-1} (XOR swizzle by batch) ---- */
            const float* src = g_hs + ((size_t)sb * NT + (t - 1)) * ND;
            #pragma unroll 8
            for (int i = 0; i < 32; i++) {
                int c = skq + 8 * i;
                float4 v = __ldcg((const float4*)(src + c * 4));
                *(float4*)&hS[sb * 1024 + ((c ^ sswz) << 2)] = v;
            }
            __syncthreads();

            /* ---- compute: warp w covers chunks C = w*32..w*32+31 ---- */
            ull acc[24];
            #pragma unroll
            for (int r = 0; r < 24; r++) acc[r] = 0ull;
            #pragma unroll 1
            for (int kc = 0; kc < 32; kc++) {
                int C = (w << 5) + kc;
                ulonglong2 h2 = *(const ulonglong2*)&hS[b * 1024 + ((C ^ bsw) << 2)];
                const float* wp = wS + (C << 2);
                #pragma unroll
                for (int r = 0; r < 24; r++) {
                    ulonglong2 w2 = *(const ulonglong2*)(wp + r * 1024);
                    acc[r] = ffma2(h2.x, w2.x, acc[r]);
                    acc[r] = ffma2(h2.y, w2.y, acc[r]);
                }
            }
            __syncthreads();   /* all hS reads done before red overlays it */

            #pragma unroll
            for (int r = 0; r < 24; r++) {
                float2 p = unpk(acc[r]);
                red[r * 256 + w * 32 + b] = p.x + p.y;
            }
            __syncthreads();

            {
                float s0 = 0.f, s1 = 0.f, s2 = 0.f;
                #pragma unroll
                for (int ww = 0; ww < 8; ww++) {
                    s0 += red[(     ejj) * 256 + ww * 32 + eb];
                    s1 += red[( 8 + ejj) * 256 + ww * 32 + eb];
                    s2 += red[(16 + ejj) * 256 + ww * 32 + eb];
                }
                ghr = s0; ghz = s1; ghn = s2;
            }
        }

        /* ---- gate epilogue ---- */
        float rr = 1.0f / (1.0f + expf(-(gir + ghr + bR)));
        float zz = 1.0f / (1.0f + expf(-(giz + ghz + bZ)));
        float nn = tanhf(gin + rr * (ghn + bN));
        float hnew = (1.0f - zz) * nn + zz * hp;
        g_hs[((size_t)eb * NT + t) * ND + ej] = hnew;
        hp = hnew;

        /* ---- grid barrier ---- */
        __threadfence();
        __syncthreads();
        if (tid == 0) {
            if (atomicAdd(&g_bar_count, 1) == GRU_BLOCKS - 1) {
                g_bar_count = 0;
                __threadfence();
                g_bar_phase = t + 1;
            } else {
                while (g_bar_phase <= t) { }
                __threadfence();
            }
        }
        __syncthreads();
    }
}

/* ---------------------------- CP loss ------------------------------------- */
__global__ __launch_bounds__(256) void k_cp(const float* __restrict__ feat,
                                            const int* __restrict__ perm) {
    int l = blockIdx.x;
    int k = blockIdx.y + 1;
    if (l >= NT - k) return;
    __shared__ __align__(16) float hS[32 * 68];
    __shared__ __align__(16) float nS[32 * 68];
    __shared__ __align__(16) float pS[32 * 68];
    __shared__ int permS[32];
    __shared__ float redS[8];
    int tid = threadIdx.x;
    if (tid < 32) permS[tid] = perm[(k - 1) * NB + tid];
    __syncthreads();

    int b = tid & 31;
    int ng = tid >> 5;
    int n0 = ng * 4;
    float acc0 = 0.f, acc1 = 0.f, acc2 = 0.f, acc3 = 0.f, accP = 0.f;

    for (int kb = 0; kb < ND; kb += 64) {
        #pragma unroll
        for (int v = 0; v < 2; v++) {
            int li = tid + 256 * v;
            int row = li >> 4;
            int kk4 = (li & 15) * 4;
            *(float4*)&hS[row * 68 + kk4] =
                *(const float4*)&g_cproj[((size_t)row * NT + l) * ND + kb + kk4];
            *(float4*)&pS[row * 68 + kk4] =
                *(const float4*)&feat[((size_t)row * NT + l + k) * ND + kb + kk4];
            *(float4*)&nS[row * 68 + kk4] =
                *(const float4*)&feat[((size_t)permS[row] * NT + l) * ND + kb + kk4];
        }
        __syncthreads();
        #pragma unroll
        for (int kk = 0; kk < 64; kk += 4) {
            float4 h4 = *(const float4*)&hS[b * 68 + kk];
            float4 m0 = *(const float4*)&nS[(n0 + 0) * 68 + kk];
            float4 m1 = *(const float4*)&nS[(n0 + 1) * 68 + kk];
            float4 m2 = *(const float4*)&nS[(n0 + 2) * 68 + kk];
            float4 m3 = *(const float4*)&nS[(n0 + 3) * 68 + kk];
            acc0 += h4.x * m0.x + h4.y * m0.y + h4.z * m0.z + h4.w * m0.w;
            acc1 += h4.x * m1.x + h4.y * m1.y + h4.z * m1.z + h4.w * m1.w;
            acc2 += h4.x * m2.x + h4.y * m2.y + h4.z * m2.z + h4.w * m2.w;
            acc3 += h4.x * m3.x + h4.y * m3.y + h4.z * m3.z + h4.w * m3.w;
            if (ng == 0) {
                float4 p4 = *(const float4*)&pS[b * 68 + kk];
                accP += h4.x * p4.x + h4.y * p4.y + h4.z * p4.z + h4.w * p4.w;
            }
        }
        __syncthreads();
    }

    float nl = 0.f;
    nl += -logf(1.0f - 1.0f / (1.0f + expf(-acc0)) + 1e-8f);
    nl += -logf(1.0f - 1.0f / (1.0f + expf(-acc1)) + 1e-8f);
    nl += -logf(1.0f - 1.0f / (1.0f + expf(-acc2)) + 1e-8f);
    nl += -logf(1.0f - 1.0f / (1.0f + expf(-acc3)) + 1e-8f);
    int lane = tid & 31;
    #pragma unroll
    for (int o = 16; o; o >>= 1) nl += __shfl_down_sync(0xffffffffu, nl, o);
    if (lane == 0) redS[tid >> 5] = nl;
    __syncthreads();
    if (tid == 0) { float s = 0.f; for (int i = 0; i < 8; i++) s += redS[i]; atomicAdd(&g_neg, s); }
    if (ng == 0) {
        float pl = -logf(1.0f / (1.0f + expf(-accP)) + 1e-8f);
        atomicAdd(&g_pos[b], pl);
    }
}

/* ----------------------------- finalize ----------------------------------- */
__global__ void k_final(float* __restrict__ outLoss) {
    int b = threadIdx.x;
    if (b < NB) {
        float cp = (g_pos[b] + 0.25f * g_neg / 1024.0f) / 1527.0f;   /* K*(T-K)=3*509 */
        float vq = 1.25f * g_sq / 16777216.0f;                        /* B*T*d */
        outLoss[b] = cp + vq;
    }
}

/* ------------------------------ launch ------------------------------------ */
extern "C" void kernel_launch(void* const* d_in, const int* in_sizes, int n_in,
                              void* d_out, int out_size) {
    (void)in_sizes; (void)n_in; (void)out_size;
    const float* feat  = (const float*)d_in[0];
    const float* cb    = (const float*)d_in[1];
    const float* Wih   = (const float*)d_in[2];
    const float* Whh   = (const float*)d_in[3];
    const float* bih   = (const float*)d_in[4];
    const float* bhh   = (const float*)d_in[5];
    const float* Wproj = (const float*)d_in[6];
    const float* bproj = (const float*)d_in[7];
    const int*   perm  = (const int*)d_in[8];

    float* out     = (float*)d_out;
    float* outq    = out;                 /* quantized (B,T,d) */
    float* outidx  = out + IDX_OFF;       /* indices as float   */
    float* outloss = out + LOSS_OFF;      /* total_loss (B,)    */

    cudaFuncSetAttribute(k_gru, cudaFuncAttributeMaxDynamicSharedMemorySize,
                         GRU_SMEM_BYTES);

    k_init<<<NCB, 256>>>(cb);
    k_quant<<<ROWS / 32, 256>>>(feat, cb, outq, outidx);
    /* gi table: (codebook @ W_ih^T + b_ih), 256 x 3072 */
    k_sgemm<<<dim3(G3 / 64, NCB / 128), 256>>>(cb, 0, Wih, bih, 0, NCB, G3, ND);
    /* persistent GRU over all 512 steps */
    k_gru<<<GRU_BLOCKS, 256, GRU_SMEM_BYTES>>>(Whh, bhh);
    /* context_proj = hs @ W_proj^T + b_proj */
    k_sgemm<<<dim3(ND / 64, ROWS / 128), 256>>>(nullptr, 1, Wproj, bproj, 1, ROWS, ND, ND);
    k_cp<<<dim3(NT - 1, 3), 256>>>(feat, perm);
    k_final<<<1, 32>>>(outloss);
}